// round 3
// baseline (speedup 1.0000x reference)
#include <cuda_runtime.h>
#include <cuda_fp16.h>
#include <cstdint>
#include <cstddef>

#define BATCH 128
#define TT 512
#define NFEAT 508
#define NCMD 4
#define IN0 512
#define H0 152
#define H1 101
#define H2 3
#define G0 456
#define G1 303
#define G1P 304
#define G2P 12
#define D1 253
#define D1P 254
#define D2 104
#define SW0X 512
#define SU0 456

// ---------------- device scratch (static, allowed) ----------------
__device__ float   g_W0xT[IN0 * SW0X];            // [512][512] input weights (fp32, GEMM)
__device__ __half2 g_W0hH[228 * 152];             // [col-pair][k] recurrent L0, fp16
__device__ __half2 g_W1H[152 * D1P];              // [col-pair][k] L1 (k padded to 254), fp16
__device__ float   g_W2T[D2 * G2P];               // [104][12]
__device__ float   g_b0c[SW0X];
__device__ float   g_b1c[G1P];
__device__ float   g_b2c[16];
__device__ float   g_U0[(size_t)BATCH * TT * SU0]; // [65536][456]

// ---------------- fast activations (abs err ~1e-6) ----------------
__device__ __forceinline__ float tanh_f(float x) {
    float e = __expf(fminf(fmaxf(2.0f * x, -80.0f), 80.0f));
    return 1.0f - __fdividef(2.0f, 1.0f + e);
}
__device__ __forceinline__ float sig_f(float x) {
    float e = __expf(fminf(fmaxf(-x, -80.0f), 80.0f));
    return __fdividef(1.0f, 1.0f + e);
}

// weight value helpers (gate order: 0=ff1 masked, 1=ff2 masked, 2=Wa+Wb)
__device__ __forceinline__ float w0_val(const float* l0W, const float* m0, int n, int col) {
    int g = n / H0, j = n % H0;
    if (g < 2) return l0W[(g * H0 + j) * 664 + col] * m0[j * 664 + col];
    return l0W[(2 * H0 + j) * 664 + col] + l0W[(3 * H0 + j) * 664 + col];
}
__device__ __forceinline__ float w1_val(const float* l1W, const float* m1, int n, int k) {
    int g = n / H1, j = n % H1;
    if (g < 2) return l1W[(g * H1 + j) * D1 + k] * m1[j * D1 + k];
    return l1W[(2 * H1 + j) * D1 + k] + l1W[(3 * H1 + j) * D1 + k];
}

// ---------------- prep ----------------
__global__ void prep_kernel(const float* __restrict__ l0W, const float* __restrict__ l0b,
                            const float* __restrict__ l1W, const float* __restrict__ l1b,
                            const float* __restrict__ l2W, const float* __restrict__ l2b,
                            const float* __restrict__ m0, const float* __restrict__ m1,
                            const float* __restrict__ m2) {
    const int R0 = IN0 * SW0X;              // 262144  W0xT
    const int R1 = R0 + 228 * 152;          // 296800  W0hH
    const int R2 = R1 + 152 * D1P;          // 335408  W1H
    const int R3 = R2 + D2 * G2P;           // 336656  W2T
    const int R4 = R3 + SW0X;               // 337168  b0c
    const int R5 = R4 + G1P;                // 337472  b1c
    const int R6 = R5 + 16;                 // 337488  b2c
    int stride = gridDim.x * blockDim.x;
    for (int i = blockIdx.x * blockDim.x + threadIdx.x; i < R6; i += stride) {
        if (i < R0) {
            int k = i / SW0X, n = i % SW0X;
            g_W0xT[i] = (n < G0) ? w0_val(l0W, m0, n, k) : 0.0f;
        } else if (i < R1) {
            int i2 = i - R0, cp = i2 / 152, k = i2 % 152;
            int col = IN0 + k;
            float v0 = w0_val(l0W, m0, 2 * cp, col);
            float v1 = w0_val(l0W, m0, 2 * cp + 1, col);
            g_W0hH[i2] = __floats2half2_rn(v0, v1);
        } else if (i < R2) {
            int i2 = i - R1, cp = i2 / D1P, k = i2 % D1P;
            float v0 = 0.0f, v1 = 0.0f;
            if (k < D1) {
                int n0 = 2 * cp, n1 = 2 * cp + 1;
                v0 = w1_val(l1W, m1, n0, k);
                if (n1 < G1) v1 = w1_val(l1W, m1, n1, k);
            }
            g_W1H[i2] = __floats2half2_rn(v0, v1);
        } else if (i < R3) {
            int i2 = i - R2, k = i2 / G2P, n = i2 % G2P;
            float v = 0.0f;
            if (n < 3 * H2) {
                int g = n / H2, j = n % H2;
                if (g < 2) v = l2W[(g * H2 + j) * D2 + k] * m2[j * D2 + k];
                else       v = l2W[(2 * H2 + j) * D2 + k] + l2W[(3 * H2 + j) * D2 + k];
            }
            g_W2T[i2] = v;
        } else if (i < R4) {
            int n = i - R3;
            float v = 0.0f;
            if (n < G0) {
                int g = n / H0, j = n % H0;
                if (g < 2) v = l0b[g * H0 + j];
                else       v = l0b[2 * H0 + j] + l0b[3 * H0 + j];
            }
            g_b0c[n] = v;
        } else if (i < R5) {
            int n = i - R4;
            float v = 0.0f;
            if (n < 3 * H1) {
                int g = n / H1, j = n % H1;
                if (g < 2) v = l1b[g * H1 + j];
                else       v = l1b[2 * H1 + j] + l1b[3 * H1 + j];
            }
            g_b1c[n] = v;
        } else {
            int n = i - R5;
            float v = 0.0f;
            if (n < 3 * H2) {
                int g = n / H2, j = n % H2;
                if (g < 2) v = l2b[g * H2 + j];
                else       v = l2b[2 * H2 + j] + l2b[3 * H2 + j];
            }
            g_b2c[n] = v;
        }
    }
}

// ---------------- phase-1 GEMM: U0 = [feat|cmd] @ W0xT + b0c ----------------
// 128x128x16 tiles, 256 threads, 8x8 micro. M=65536, K=512, N=456 (4 tiles of 128).
__global__ void __launch_bounds__(256) gemm_u0(const float* __restrict__ feat,
                                               const float* __restrict__ cmd) {
    __shared__ float As[128][20];   // [row][k], padded
    __shared__ float Bs[16][132];   // [k][n], padded
    int tid = threadIdx.x;
    int tx = tid & 15, ty = tid >> 4;
    int m0 = blockIdx.y * 128, n0 = blockIdx.x * 128;

    float acc[8][8];
#pragma unroll
    for (int i = 0; i < 8; i++)
#pragma unroll
        for (int j = 0; j < 8; j++) acc[i][j] = 0.0f;

    for (int kc = 0; kc < IN0; kc += 16) {
#pragma unroll
        for (int it = 0; it < 2; it++) {
            int lin = tid * 2 + it;
            int row = lin >> 2;
            int kq = (lin & 3) << 2;
            int m = m0 + row, k = kc + kq;
            float4 v;
            if (k < NFEAT) v = *(const float4*)(feat + (size_t)m * NFEAT + k);
            else           v = *(const float4*)(cmd + (size_t)m * NCMD);
            *(float4*)&As[row][kq] = v;
        }
#pragma unroll
        for (int it = 0; it < 2; it++) {
            int lin = tid * 2 + it;
            int kl = lin >> 5;
            int n4 = (lin & 31) << 2;
            float4 v = *(const float4*)(g_W0xT + (kc + kl) * SW0X + n0 + n4);
            *(float4*)&Bs[kl][n4] = v;
        }
        __syncthreads();
#pragma unroll
        for (int kl = 0; kl < 16; kl++) {
            float a[8];
#pragma unroll
            for (int i = 0; i < 8; i++) a[i] = As[ty * 8 + i][kl];
            float4 b0 = *(float4*)&Bs[kl][tx * 8];
            float4 b1 = *(float4*)&Bs[kl][tx * 8 + 4];
#pragma unroll
            for (int i = 0; i < 8; i++) {
                acc[i][0] = fmaf(a[i], b0.x, acc[i][0]);
                acc[i][1] = fmaf(a[i], b0.y, acc[i][1]);
                acc[i][2] = fmaf(a[i], b0.z, acc[i][2]);
                acc[i][3] = fmaf(a[i], b0.w, acc[i][3]);
                acc[i][4] = fmaf(a[i], b1.x, acc[i][4]);
                acc[i][5] = fmaf(a[i], b1.y, acc[i][5]);
                acc[i][6] = fmaf(a[i], b1.z, acc[i][6]);
                acc[i][7] = fmaf(a[i], b1.w, acc[i][7]);
            }
        }
        __syncthreads();
    }
    int n = n0 + tx * 8;
    if (n < SU0) {   // 456 % 8 == 0, so vectors never straddle the edge
        float4 bia0 = *(const float4*)(g_b0c + n);
        float4 bia1 = *(const float4*)(g_b0c + n + 4);
#pragma unroll
        for (int i = 0; i < 8; i++) {
            int m = m0 + ty * 8 + i;
            float4 s0 = make_float4(acc[i][0] + bia0.x, acc[i][1] + bia0.y,
                                    acc[i][2] + bia0.z, acc[i][3] + bia0.w);
            float4 s1 = make_float4(acc[i][4] + bia1.x, acc[i][5] + bia1.y,
                                    acc[i][6] + bia1.z, acc[i][7] + bia1.w);
            *(float4*)(g_U0 + (size_t)m * SU0 + n) = s0;
            *(float4*)(g_U0 + (size_t)m * SU0 + n + 4) = s1;
        }
    }
}

// ---------------- scan: 64 blocks x 512 threads, 2 rows / block ----------------
// smem layout (float units)
#define OFF_W0C 0                      // half2[228*152] = 34656 float slots
#define OFF_W2C 34656                  // float[104*12]  = 1248
#define OFF_B1C 35904                  // float[304]
#define OFF_B2C 36208                  // float[16]
#define OFF_D1  36224                  // float2[254] = 508 (16B aligned)
#define OFF_D2  36732                  // float2[104] = 208
#define OFF_P0  36940                  // float4[2*228] = 1824 (16B aligned)
#define OFF_P1  38764                  // float4[3*152] = 1824 (16B aligned)
#define OFF_P2  40588                  // float2[8*9] = 144
#define SMEM_FLOATS 40732
#define SMEM_BYTES (SMEM_FLOATS * 4)   // 162928 B

__global__ void __launch_bounds__(512, 1) scan_kernel(float* __restrict__ out) {
    extern __shared__ float sm[];
    __half2* W0c = (__half2*)(sm + OFF_W0C);   // [228][152]
    float*   W2c = sm + OFF_W2C;
    float*   b1c = sm + OFF_B1C;
    float*   b2c = sm + OFF_B2C;
    float*   d1f = sm + OFF_D1;                // float2[254] viewed as floats
    float2*  d1s = (float2*)(sm + OFF_D1);
    float2*  d2s = (float2*)(sm + OFF_D2);
    float4*  p0  = (float4*)(sm + OFF_P0);
    float4*  p1  = (float4*)(sm + OFF_P1);
    float2*  p2  = (float2*)(sm + OFF_P2);

    int tid = threadIdx.x;
    int rowA = blockIdx.x * 2, rowB = rowA + 1;

    {
        const uint32_t* src = (const uint32_t*)g_W0hH;
        uint32_t* dst = (uint32_t*)W0c;
        for (int i = tid; i < 228 * 152; i += 512) dst[i] = src[i];
    }
    for (int i = tid; i < D2 * G2P; i += 512) W2c[i] = g_W2T[i];
    if (tid < G1P) b1c[tid] = g_b1c[tid];
    if (tid < 16) b2c[tid] = g_b2c[tid];
    for (int i = tid; i < D1P; i += 512) d1s[i] = make_float2(0.f, 0.f);
    for (int i = tid; i < D2; i += 512) d2s[i] = make_float2(0.f, 0.f);
    __syncthreads();

    const float* U0a = g_U0 + (size_t)rowA * TT * SU0;
    const float* U0b = g_U0 + (size_t)rowB * TT * SU0;

    int cp0 = tid % 228, ks0 = tid / 228;   // L0: 228 col-pairs x 2 k-chunks of 76
    int cp1 = tid % 152, ks1 = tid / 152;   // L1: 152 col-pairs x 3 k-chunks (86/84/84)
    int j2  = tid % 9,   ks2 = tid / 9;     // L2: 9 cols x 8 k-chunks of 13

    int k0c1 = (ks1 == 0) ? 0 : (ks1 == 1 ? 86 : 170);
    int k1c1 = (ks1 == 0) ? 86 : (ks1 == 1 ? 170 : D1P);

    for (int t = 0; t < TT; t++) {
        // ---- A: layer-0 gate partials (weights fp16 in smem, [cp][k]) ----
        if (tid < 456) {
            int c0 = cp0 * 2;
            const __half2* Wp = W0c + cp0 * 152;
            float4 acc;
            if (ks0 == 0) {
                float2 va = *(const float2*)(U0a + (size_t)t * SU0 + c0);
                float2 vb = *(const float2*)(U0b + (size_t)t * SU0 + c0);
                acc = make_float4(va.x, vb.x, va.y, vb.y);
            } else {
                acc = make_float4(0.f, 0.f, 0.f, 0.f);
            }
            int k0 = ks0 * 76, k1 = k0 + 76;
#pragma unroll 8
            for (int k = k0; k < k1; k += 2) {
                uint2 wr = *(const uint2*)(Wp + k);
                float2 w0 = __half22float2(*(__half2*)&wr.x);   // k:   (c0, c0+1)
                float2 w1 = __half22float2(*(__half2*)&wr.y);   // k+1: (c0, c0+1)
                float4 d = *(const float4*)(d1f + 2 * k);       // (hA[k],hB[k],hA[k+1],hB[k+1])
                acc.x = fmaf(w0.x, d.x, acc.x); acc.y = fmaf(w0.x, d.y, acc.y);
                acc.z = fmaf(w0.y, d.x, acc.z); acc.w = fmaf(w0.y, d.y, acc.w);
                acc.x = fmaf(w1.x, d.z, acc.x); acc.y = fmaf(w1.x, d.w, acc.y);
                acc.z = fmaf(w1.y, d.z, acc.z); acc.w = fmaf(w1.y, d.w, acc.w);
            }
            p0[ks0 * 228 + cp0] = acc;
        }
        __syncthreads();
        // ---- B: h0 update ----
        if (tid < H0) {
            int j = tid;
            float ga[3][2];
#pragma unroll
            for (int g = 0; g < 3; g++) {
                int c = g * H0 + j;
                int cp = c >> 1, lane = (c & 1) << 1;
                const float* q0 = (const float*)&p0[cp];
                const float* q1 = (const float*)&p0[228 + cp];
                ga[g][0] = q0[lane] + q1[lane];
                ga[g][1] = q0[lane + 1] + q1[lane + 1];
            }
            float2 h;
            { float s = sig_f(ga[2][0]); h.x = tanh_f(ga[0][0]) * (1.f - s) + s * tanh_f(ga[1][0]); }
            { float s = sig_f(ga[2][1]); h.y = tanh_f(ga[0][1]) * (1.f - s) + s * tanh_f(ga[1][1]); }
            d1s[j] = h;
        }
        __syncthreads();
        // ---- C: layer-1 gate partials (weights fp16 from L2, [cp][k]) ----
        if (tid < 456) {
            int c0 = cp1 * 2;
            const __half2* Wp = g_W1H + cp1 * D1P;
            float4 acc = (ks1 == 0) ? make_float4(b1c[c0], b1c[c0], b1c[c0 + 1], b1c[c0 + 1])
                                    : make_float4(0.f, 0.f, 0.f, 0.f);
#pragma unroll 8
            for (int k = k0c1; k < k1c1; k += 2) {
                uint2 wr = *(const uint2*)(Wp + k);
                float2 w0 = __half22float2(*(__half2*)&wr.x);
                float2 w1 = __half22float2(*(__half2*)&wr.y);
                float4 d = *(const float4*)(d1f + 2 * k);
                acc.x = fmaf(w0.x, d.x, acc.x); acc.y = fmaf(w0.x, d.y, acc.y);
                acc.z = fmaf(w0.y, d.x, acc.z); acc.w = fmaf(w0.y, d.y, acc.w);
                acc.x = fmaf(w1.x, d.z, acc.x); acc.y = fmaf(w1.x, d.w, acc.y);
                acc.z = fmaf(w1.y, d.z, acc.z); acc.w = fmaf(w1.y, d.w, acc.w);
            }
            p1[ks1 * 152 + cp1] = acc;
        }
        __syncthreads();
        // ---- D: h1 update ----
        if (tid < H1) {
            int j = tid;
            float ga[3][2];
#pragma unroll
            for (int g = 0; g < 3; g++) {
                int c = g * H1 + j;
                int cp = c >> 1, lane = (c & 1) << 1;
                const float* q0 = (const float*)&p1[cp];
                const float* q1 = (const float*)&p1[152 + cp];
                const float* q2 = (const float*)&p1[304 + cp];
                ga[g][0] = q0[lane] + q1[lane] + q2[lane];
                ga[g][1] = q0[lane + 1] + q1[lane + 1] + q2[lane + 1];
            }
            float2 h;
            { float s = sig_f(ga[2][0]); h.x = tanh_f(ga[0][0]) * (1.f - s) + s * tanh_f(ga[1][0]); }
            { float s = sig_f(ga[2][1]); h.y = tanh_f(ga[0][1]) * (1.f - s) + s * tanh_f(ga[1][1]); }
            d1s[H0 + j] = h;
            d2s[j] = h;
        }
        __syncthreads();
        // ---- E: layer-2 gate partials ----
        if (tid < 72) {
            int k0 = ks2 * 13, k1 = k0 + 13;
            float2 acc = (ks2 == 0) ? make_float2(b2c[j2], b2c[j2]) : make_float2(0.f, 0.f);
#pragma unroll
            for (int k = k0; k < k1; k++) {
                float w = W2c[k * G2P + j2];
                float2 d = d2s[k];
                acc.x = fmaf(w, d.x, acc.x); acc.y = fmaf(w, d.y, acc.y);
            }
            p2[ks2 * 9 + j2] = acc;
        }
        __syncthreads();
        // ---- F: h2 update + control outputs ----
        if (tid < 3) {
            int j = tid;
            float2 f1 = make_float2(0.f, 0.f), f2 = make_float2(0.f, 0.f), tg = make_float2(0.f, 0.f);
#pragma unroll
            for (int s = 0; s < 8; s++) {
                float2 a = p2[s * 9 + j];     f1.x += a.x; f1.y += a.y;
                float2 b = p2[s * 9 + 3 + j]; f2.x += b.x; f2.y += b.y;
                float2 c = p2[s * 9 + 6 + j]; tg.x += c.x; tg.y += c.y;
            }
            float2 h;
            { float s = sig_f(tg.x); h.x = tanh_f(f1.x) * (1.f - s) + s * tanh_f(f2.x); }
            { float s = sig_f(tg.y); h.y = tanh_f(f1.y) * (1.f - s) + s * tanh_f(f2.y); }
            d2s[H1 + j] = h;
            float ca = (j == 0) ? tanh_f(h.x) : sig_f(h.x);
            float cb = (j == 0) ? tanh_f(h.y) : sig_f(h.y);
            out[((size_t)rowA * TT + t) * 3 + j] = ca;
            out[((size_t)rowB * TT + t) * 3 + j] = cb;
        }
        __syncthreads();
    }

    // final hidden state hx = [h0 | h1 | h2], [B][256]
    float* hx = out + (size_t)BATCH * TT * 3;
    if (tid < D1) {
        float2 h = d1s[tid];
        hx[rowA * 256 + tid] = h.x;
        hx[rowB * 256 + tid] = h.y;
    } else if (tid < 256) {
        int j = tid - D1;
        float2 h = d2s[H1 + j];
        hx[rowA * 256 + D1 + j] = h.x;
        hx[rowB * 256 + D1 + j] = h.y;
    }
}

// ---------------- launch ----------------
extern "C" void kernel_launch(void* const* d_in, const int* in_sizes, int n_in,
                              void* d_out, int out_size) {
    const float* feat = (const float*)d_in[0];
    const float* cmd  = (const float*)d_in[1];
    const float* l0W  = (const float*)d_in[2];
    const float* l0b  = (const float*)d_in[3];
    const float* l1W  = (const float*)d_in[4];
    const float* l1b  = (const float*)d_in[5];
    const float* l2W  = (const float*)d_in[6];
    const float* l2b  = (const float*)d_in[7];
    const float* m0   = (const float*)d_in[8];
    const float* m1   = (const float*)d_in[9];
    const float* m2   = (const float*)d_in[10];
    float* out = (float*)d_out;

    prep_kernel<<<256, 256>>>(l0W, l0b, l1W, l1b, l2W, l2b, m0, m1, m2);

    dim3 gg(4, 512);
    gemm_u0<<<gg, 256>>>(feat, cmd);

    cudaFuncSetAttribute(scan_kernel, cudaFuncAttributeMaxDynamicSharedMemorySize, SMEM_BYTES);
    scan_kernel<<<BATCH / 2, 512, SMEM_BYTES>>>(out);
}

// round 6
// speedup vs baseline: 1.9161x; 1.9161x over previous
#include <cuda_runtime.h>
#include <cuda_fp16.h>
#include <cstdint>
#include <cstddef>

#define BATCH 128
#define TT 512
#define NFEAT 508
#define NCMD 4
#define IN0 512
#define H0 152
#define H1 101
#define H2 3
#define G0 456
#define G1 303
#define G1P 304
#define D1 253
#define D2 104
#define SW0X 512
#define SU0 456

// ---------------- device scratch (static, allowed) ----------------
__device__ float   g_W0xT[IN0 * SW0X];            // [512][512] input weights (fp32, GEMM)
__device__ __half2 g_W0pA[48 * 456];              // [k2][c] k2<48  (k<96)  recurrent L0
__device__ __half2 g_W0pB[28 * 456];              // [k2-48][c]     (k 96..151)
__device__ __half2 g_W1p[127 * 304];              // [k2][c] k pairs over 253 (pad k=253 -> 0)
__device__ float   g_W2T[D2 * 12];                // [104][12]
__device__ float   g_b0c[SW0X];
__device__ float   g_b1c[G1P];
__device__ float   g_b2c[16];
__device__ float   g_U0[(size_t)BATCH * TT * SU0]; // [65536][456]

// ---------------- fast activations (abs err ~1e-6) ----------------
__device__ __forceinline__ float tanh_f(float x) {
    float e = __expf(fminf(fmaxf(2.0f * x, -80.0f), 80.0f));
    return 1.0f - __fdividef(2.0f, 1.0f + e);
}
__device__ __forceinline__ float sig_f(float x) {
    float e = __expf(fminf(fmaxf(-x, -80.0f), 80.0f));
    return __fdividef(1.0f, 1.0f + e);
}

// weight helpers (gate order: 0=ff1 masked, 1=ff2 masked, 2=Wa+Wb)
__device__ __forceinline__ float w0_val(const float* l0W, const float* m0, int n, int col) {
    int g = n / H0, j = n % H0;
    if (g < 2) return l0W[(g * H0 + j) * 664 + col] * m0[j * 664 + col];
    return l0W[(2 * H0 + j) * 664 + col] + l0W[(3 * H0 + j) * 664 + col];
}
__device__ __forceinline__ float w1_val(const float* l1W, const float* m1, int n, int k) {
    int g = n / H1, j = n % H1;
    if (g < 2) return l1W[(g * H1 + j) * D1 + k] * m1[j * D1 + k];
    return l1W[(2 * H1 + j) * D1 + k] + l1W[(3 * H1 + j) * D1 + k];
}

// ---------------- prep ----------------
__global__ void prep_kernel(const float* __restrict__ l0W, const float* __restrict__ l0b,
                            const float* __restrict__ l1W, const float* __restrict__ l1b,
                            const float* __restrict__ l2W, const float* __restrict__ l2b,
                            const float* __restrict__ m0, const float* __restrict__ m1,
                            const float* __restrict__ m2) {
    const int R0 = IN0 * SW0X;              // 262144  W0xT
    const int R1 = R0 + 48 * 456;           // 284032  W0pA
    const int R2 = R1 + 28 * 456;           // 296800  W0pB
    const int R3 = R2 + 127 * 304;          // 335408  W1p
    const int R4 = R3 + D2 * 12;            // 336656  W2T
    const int R5 = R4 + SW0X;               // 337168  b0c
    const int R6 = R5 + G1P;                // 337472  b1c
    const int R7 = R6 + 16;                 // 337488  b2c
    int stride = gridDim.x * blockDim.x;
    for (int i = blockIdx.x * blockDim.x + threadIdx.x; i < R7; i += stride) {
        if (i < R0) {
            int k = i / SW0X, n = i % SW0X;
            g_W0xT[i] = (n < G0) ? w0_val(l0W, m0, n, k) : 0.0f;
        } else if (i < R1) {
            int i2 = i - R0, k2 = i2 / 456, c = i2 % 456;
            int col = IN0 + 2 * k2;
            g_W0pA[i2] = __floats2half2_rn(w0_val(l0W, m0, c, col),
                                           w0_val(l0W, m0, c, col + 1));
        } else if (i < R2) {
            int i2 = i - R1, k2 = 48 + i2 / 456, c = i2 % 456;
            int col = IN0 + 2 * k2;
            g_W0pB[i2] = __floats2half2_rn(w0_val(l0W, m0, c, col),
                                           w0_val(l0W, m0, c, col + 1));
        } else if (i < R3) {
            int i2 = i - R2, k2 = i2 / 304, c = i2 % 304;
            int k0 = 2 * k2, k1 = k0 + 1;
            float v0 = 0.0f, v1 = 0.0f;
            if (c < G1) {
                v0 = w1_val(l1W, m1, c, k0);
                if (k1 < D1) v1 = w1_val(l1W, m1, c, k1);
            }
            g_W1p[i2] = __floats2half2_rn(v0, v1);
        } else if (i < R4) {
            int i2 = i - R3, k = i2 / 12, n = i2 % 12;
            float v = 0.0f;
            if (n < 3 * H2) {
                int g = n / H2, j = n % H2;
                if (g < 2) v = l2W[(g * H2 + j) * D2 + k] * m2[j * D2 + k];
                else       v = l2W[(2 * H2 + j) * D2 + k] + l2W[(3 * H2 + j) * D2 + k];
            }
            g_W2T[i2] = v;
        } else if (i < R5) {
            int n = i - R4;
            float v = 0.0f;
            if (n < G0) {
                int g = n / H0, j = n % H0;
                if (g < 2) v = l0b[g * H0 + j];
                else       v = l0b[2 * H0 + j] + l0b[3 * H0 + j];
            }
            g_b0c[n] = v;
        } else if (i < R6) {
            int n = i - R5;
            float v = 0.0f;
            if (n < 3 * H1) {
                int g = n / H1, j = n % H1;
                if (g < 2) v = l1b[g * H1 + j];
                else       v = l1b[2 * H1 + j] + l1b[3 * H1 + j];
            }
            g_b1c[n] = v;
        } else {
            int n = i - R6;
            float v = 0.0f;
            if (n < 3 * H2) {
                int g = n / H2, j = n % H2;
                if (g < 2) v = l2b[g * H2 + j];
                else       v = l2b[2 * H2 + j] + l2b[3 * H2 + j];
            }
            g_b2c[n] = v;
        }
    }
}

// ---------------- phase-1 GEMM: U0 = [feat|cmd] @ W0xT + b0c ----------------
__global__ void __launch_bounds__(256) gemm_u0(const float* __restrict__ feat,
                                               const float* __restrict__ cmd) {
    __shared__ float As[128][20];
    __shared__ float Bs[16][132];
    int tid = threadIdx.x;
    int tx = tid & 15, ty = tid >> 4;
    int m0 = blockIdx.y * 128, n0 = blockIdx.x * 128;

    float acc[8][8];
#pragma unroll
    for (int i = 0; i < 8; i++)
#pragma unroll
        for (int j = 0; j < 8; j++) acc[i][j] = 0.0f;

    for (int kc = 0; kc < IN0; kc += 16) {
#pragma unroll
        for (int it = 0; it < 2; it++) {
            int lin = tid * 2 + it;
            int row = lin >> 2;
            int kq = (lin & 3) << 2;
            int m = m0 + row, k = kc + kq;
            float4 v;
            if (k < NFEAT) v = *(const float4*)(feat + (size_t)m * NFEAT + k);
            else           v = *(const float4*)(cmd + (size_t)m * NCMD);
            *(float4*)&As[row][kq] = v;
        }
#pragma unroll
        for (int it = 0; it < 2; it++) {
            int lin = tid * 2 + it;
            int kl = lin >> 5;
            int n4 = (lin & 31) << 2;
            float4 v = *(const float4*)(g_W0xT + (kc + kl) * SW0X + n0 + n4);
            *(float4*)&Bs[kl][n4] = v;
        }
        __syncthreads();
#pragma unroll
        for (int kl = 0; kl < 16; kl++) {
            float a[8];
#pragma unroll
            for (int i = 0; i < 8; i++) a[i] = As[ty * 8 + i][kl];
            float4 b0 = *(float4*)&Bs[kl][tx * 8];
            float4 b1 = *(float4*)&Bs[kl][tx * 8 + 4];
#pragma unroll
            for (int i = 0; i < 8; i++) {
                acc[i][0] = fmaf(a[i], b0.x, acc[i][0]);
                acc[i][1] = fmaf(a[i], b0.y, acc[i][1]);
                acc[i][2] = fmaf(a[i], b0.z, acc[i][2]);
                acc[i][3] = fmaf(a[i], b0.w, acc[i][3]);
                acc[i][4] = fmaf(a[i], b1.x, acc[i][4]);
                acc[i][5] = fmaf(a[i], b1.y, acc[i][5]);
                acc[i][6] = fmaf(a[i], b1.z, acc[i][6]);
                acc[i][7] = fmaf(a[i], b1.w, acc[i][7]);
            }
        }
        __syncthreads();
    }
    int n = n0 + tx * 8;
    if (n < SU0) {
        float4 bia0 = *(const float4*)(g_b0c + n);
        float4 bia1 = *(const float4*)(g_b0c + n + 4);
#pragma unroll
        for (int i = 0; i < 8; i++) {
            int m = m0 + ty * 8 + i;
            float4 s0 = make_float4(acc[i][0] + bia0.x, acc[i][1] + bia0.y,
                                    acc[i][2] + bia0.z, acc[i][3] + bia0.w);
            float4 s1 = make_float4(acc[i][4] + bia1.x, acc[i][5] + bia1.y,
                                    acc[i][6] + bia1.z, acc[i][7] + bia1.w);
            *(float4*)(g_U0 + (size_t)m * SU0 + n) = s0;
            *(float4*)(g_U0 + (size_t)m * SU0 + n + 4) = s1;
        }
    }
}

// ---------------- scan: 128 blocks x 512 threads, 1 row / block ----------------
#define OFF_W1  0            // half2[127*304] = 38608 slots
#define OFF_W0B 38608        // half2[28*456]  = 12768
#define OFF_W2  51376        // float[104*12]  = 1248
#define OFF_B1  52624        // float[304]
#define OFF_B2  52928        // float[16]
#define OFF_D1  52944        // float[256]  (d1[253..255]=0 always)
#define OFF_D2  53200        // float[104]
#define OFF_G0  53304        // float[456]
#define OFF_G1  53760        // float[304]
#define OFF_P2  54064        // float[72]
#define SMEM_FLOATS 54136
#define SMEM_BYTES (SMEM_FLOATS * 4)   // 216544 B

__global__ void __launch_bounds__(512, 1) scan_kernel(float* __restrict__ out) {
    extern __shared__ float sm[];
    uint32_t* sW1  = (uint32_t*)(sm + OFF_W1);
    uint32_t* sW0B = (uint32_t*)(sm + OFF_W0B);
    float*    sW2  = sm + OFF_W2;
    float*    b1s  = sm + OFF_B1;
    float*    b2s  = sm + OFF_B2;
    float*    d1   = sm + OFF_D1;
    float*    d2   = sm + OFF_D2;
    float*    gate0 = sm + OFF_G0;
    float*    gate1 = sm + OFF_G1;
    float*    p2   = sm + OFF_P2;

    int tid = threadIdx.x;
    int row = blockIdx.x;

    // ---- init smem ----
    {
        const uint32_t* src1 = (const uint32_t*)g_W1p;
        for (int i = tid; i < 127 * 304; i += 512) sW1[i] = src1[i];
        const uint32_t* src0 = (const uint32_t*)g_W0pB;
        for (int i = tid; i < 28 * 456; i += 512) sW0B[i] = src0[i];
        for (int i = tid; i < D2 * 12; i += 512) sW2[i] = g_W2T[i];
        if (tid < G1P) b1s[tid] = g_b1c[tid];
        if (tid < 16) b2s[tid] = g_b2c[tid];
        if (tid < 256) d1[tid] = 0.0f;
        if (tid < D2) d2[tid] = 0.0f;
    }

    // ---- persistent register weights: first 96 k of W0h ----
    uint32_t w0r[48];
    if (tid < 456) {
#pragma unroll
        for (int k2 = 0; k2 < 48; k2++)
            w0r[k2] = ((const uint32_t*)g_W0pA)[k2 * 456 + tid];
    } else {
#pragma unroll
        for (int k2 = 0; k2 < 48; k2++) w0r[k2] = 0;
    }

    const float* U0row = g_U0 + (size_t)row * TT * SU0;
    float u_cur = (tid < 456) ? U0row[tid] : 0.0f;
    float u_nxt = 0.0f;

    int j2 = tid % 9, ks2 = tid / 9;   // phase E mapping (tid<72)

    __syncthreads();

    for (int t = 0; t < TT; t++) {
        // ==== phase A (L0 gemv) || phase F(t-1) in threads 480..482 ====
        if (tid < 456) {
            float acc0 = u_cur, acc1 = 0.0f;
#pragma unroll
            for (int k2 = 0; k2 < 48; k2++) {
                float2 w = __half22float2(*(__half2*)&w0r[k2]);
                float2 d = *(const float2*)(d1 + 2 * k2);
                acc0 = fmaf(w.x, d.x, acc0);
                acc1 = fmaf(w.y, d.y, acc1);
            }
#pragma unroll 7
            for (int k2 = 0; k2 < 28; k2++) {
                uint32_t wr = sW0B[k2 * 456 + tid];
                float2 w = __half22float2(*(__half2*)&wr);
                float2 d = *(const float2*)(d1 + 96 + 2 * k2);
                acc0 = fmaf(w.x, d.x, acc0);
                acc1 = fmaf(w.y, d.y, acc1);
            }
            gate0[tid] = acc0 + acc1;
            if (t + 1 < TT) u_nxt = U0row[(size_t)(t + 1) * SU0 + tid];
        } else if (tid >= 480 && tid < 483 && t > 0) {
            int j = tid - 480;
            float f1 = 0.f, f2 = 0.f, tg = 0.f;
#pragma unroll
            for (int s = 0; s < 8; s++) {
                f1 += p2[s * 9 + j];
                f2 += p2[s * 9 + 3 + j];
                tg += p2[s * 9 + 6 + j];
            }
            float s = sig_f(tg);
            float h = tanh_f(f1) * (1.f - s) + s * tanh_f(f2);
            d2[101 + j] = h;
            out[((size_t)row * TT + (t - 1)) * 3 + j] = (j == 0) ? tanh_f(h) : sig_f(h);
        }
        __syncthreads();

        // ==== phase B: h0 update ====
        if (tid < H0) {
            float g0 = gate0[tid], g1 = gate0[H0 + tid], gt = gate0[2 * H0 + tid];
            float s = sig_f(gt);
            d1[tid] = tanh_f(g0) * (1.f - s) + s * tanh_f(g1);
        }
        __syncthreads();

        // ==== phase C: L1 gemv ====
        if (tid < G1P) {
            float acc0 = b1s[tid], acc1 = 0.0f;
#pragma unroll 8
            for (int k2 = 0; k2 < 127; k2++) {
                uint32_t wr = sW1[k2 * 304 + tid];
                float2 w = __half22float2(*(__half2*)&wr);
                float2 d = *(const float2*)(d1 + 2 * k2);
                acc0 = fmaf(w.x, d.x, acc0);
                acc1 = fmaf(w.y, d.y, acc1);
            }
            gate1[tid] = acc0 + acc1;
        }
        __syncthreads();

        // ==== phase D: h1 update ====
        if (tid < H1) {
            float g0 = gate1[tid], g1 = gate1[H1 + tid], gt = gate1[2 * H1 + tid];
            float s = sig_f(gt);
            float h = tanh_f(g0) * (1.f - s) + s * tanh_f(g1);
            d1[H0 + tid] = h;
            d2[tid] = h;
        }
        __syncthreads();

        // ==== phase E: L2 gemv partials ====
        if (tid < 72) {
            int k0 = ks2 * 13, k1 = k0 + 13;
            float acc = (ks2 == 0) ? b2s[j2] : 0.0f;
#pragma unroll
            for (int k = k0; k < k1; k++)
                acc = fmaf(sW2[k * 12 + j2], d2[k], acc);
            p2[ks2 * 9 + j2] = acc;
        }
        u_cur = u_nxt;
        __syncthreads();
    }

    // ---- final F (t = TT-1) ----
    if (tid >= 480 && tid < 483) {
        int j = tid - 480;
        float f1 = 0.f, f2 = 0.f, tg = 0.f;
#pragma unroll
        for (int s = 0; s < 8; s++) {
            f1 += p2[s * 9 + j];
            f2 += p2[s * 9 + 3 + j];
            tg += p2[s * 9 + 6 + j];
        }
        float s = sig_f(tg);
        float h = tanh_f(f1) * (1.f - s) + s * tanh_f(f2);
        d2[101 + j] = h;
        out[((size_t)row * TT + (TT - 1)) * 3 + j] = (j == 0) ? tanh_f(h) : sig_f(h);
    }
    __syncthreads();

    // ---- final hidden state hx = [h0 | h1 | h2] ----
    float* hx = out + (size_t)BATCH * TT * 3;
    if (tid < D1) {
        hx[row * 256 + tid] = d1[tid];
    } else if (tid < 256) {
        hx[row * 256 + tid] = d2[101 + (tid - D1)];
    }
}

// ---------------- launch ----------------
extern "C" void kernel_launch(void* const* d_in, const int* in_sizes, int n_in,
                              void* d_out, int out_size) {
    const float* feat = (const float*)d_in[0];
    const float* cmd  = (const float*)d_in[1];
    const float* l0W  = (const float*)d_in[2];
    const float* l0b  = (const float*)d_in[3];
    const float* l1W  = (const float*)d_in[4];
    const float* l1b  = (const float*)d_in[5];
    const float* l2W  = (const float*)d_in[6];
    const float* l2b  = (const float*)d_in[7];
    const float* m0   = (const float*)d_in[8];
    const float* m1   = (const float*)d_in[9];
    const float* m2   = (const float*)d_in[10];
    float* out = (float*)d_out;

    prep_kernel<<<256, 256>>>(l0W, l0b, l1W, l1b, l2W, l2b, m0, m1, m2);

    dim3 gg(4, 512);
    gemm_u0<<<gg, 256>>>(feat, cmd);

    cudaFuncSetAttribute(scan_kernel, cudaFuncAttributeMaxDynamicSharedMemorySize, SMEM_BYTES);
    scan_kernel<<<BATCH, 512, SMEM_BYTES>>>(out);
}